// round 14
// baseline (speedup 1.0000x reference)
#include <cuda_runtime.h>
#include <cuda_fp16.h>
#include <math.h>
#include <stdint.h>

#define NN 10000
#define NE 160000
#define ET (NN + NE)

// ---------------- scratch (device globals; referenced by symbol ONLY in device code) ----------------
__device__ __half g_feath[NN * 256];    // layer input features fp16 (row-major, stride = Kp)
__device__ __half g_wh[2048 * 256];     // W^T fp16, [HC][Kp] K-major
__device__ __half g_hbufh[NN * 2048];   // h = X @ W  fp16 (row-major, stride = H*C)
__device__ float  g_hs[NN * 16];
__device__ float  g_hd[NN * 16];
__device__ int    g_cnt[NN];
__device__ int    g_cur[NN];
__device__ int    g_off[NN + 1];
__device__ int    g_csr[ET];
__device__ float  g_cb1[64 * 64 * 64];
__device__ float  g_cb2[64 * 64 * 64];
__device__ float  g_gf[24];
__device__ unsigned char g_bflags[NN];
__device__ int    g_is64;

__device__ __forceinline__ float selu_f(float v) {
    const float sc = 1.0507009873554805f;
    const float al = 1.6732632423543772f;
    return v > 0.f ? sc * v : sc * al * (expf(v) - 1.f);
}

__device__ __forceinline__ int edge_at(const void* ei, int idx) {
    if (g_is64) return (int)((const long long*)ei)[idx];
    return ((const int*)ei)[idx];
}

// ---------------- CSR init + dtype detection ----------------
__global__ void init_detect_k(const void* __restrict__ ei) {
    int i = blockIdx.x * 256 + threadIdx.x;
    if (i < NN) { g_cnt[i] = 1; g_cur[i] = 0; }
    if (blockIdx.x == 0) {
        __shared__ int nz;
        if (threadIdx.x == 0) nz = 0;
        __syncthreads();
        const int* p = (const int*)ei;
        int found = 0;
        for (int j = threadIdx.x; j < 4096; j += 256)
            if (p[2 * j + 1] != 0) found = 1;
        if (found) atomicOr(&nz, 1);
        __syncthreads();
        if (threadIdx.x == 0) g_is64 = nz ? 0 : 1;
    }
}

__global__ void csr_count_k(const void* __restrict__ ei) {
    int e = blockIdx.x * 256 + threadIdx.x;
    if (e < NE) atomicAdd(&g_cnt[edge_at(ei, NE + e)], 1);
}

__global__ void csr_scan_k() {
    __shared__ int wsum[32];
    int tid = threadIdx.x;
    const int per = 10;
    int start = tid * per;
    int s = 0;
#pragma unroll
    for (int j = 0; j < per; j++) { int idx = start + j; if (idx < NN) s += g_cnt[idx]; }
    int lane = tid & 31, warp = tid >> 5;
    int v = s;
#pragma unroll
    for (int o = 1; o < 32; o <<= 1) {
        int t = __shfl_up_sync(0xffffffffu, v, o);
        if (lane >= o) v += t;
    }
    if (lane == 31) wsum[warp] = v;
    __syncthreads();
    if (warp == 0) {
        int w = wsum[lane];
#pragma unroll
        for (int o = 1; o < 32; o <<= 1) {
            int t = __shfl_up_sync(0xffffffffu, w, o);
            if (lane >= o) w += t;
        }
        wsum[lane] = w;
    }
    __syncthreads();
    int base = (warp ? wsum[warp - 1] : 0) + (v - s);
    int run = base;
#pragma unroll
    for (int j = 0; j < per; j++) {
        int idx = start + j;
        if (idx < NN) { g_off[idx] = run; run += g_cnt[idx]; }
    }
    if (tid == 0) g_off[NN] = wsum[31];
}

__global__ void csr_fill_k(const void* __restrict__ ei) {
    int idx = blockIdx.x * 256 + threadIdx.x;
    if (idx >= ET) return;
    int s, d;
    if (idx < NN) { s = idx; d = idx; }
    else {
        int e = idx - NN;
        s = edge_at(ei, e);
        d = edge_at(ei, NE + e);
    }
    int pos = g_off[d] + atomicAdd(&g_cur[d], 1);
    g_csr[pos] = s;
}

// ---------------- CNN ----------------
__global__ void conv3x3_k(const float* __restrict__ ext_in, int in_sel, int out_sel,
                          const float* __restrict__ w, const float* __restrict__ b, int IC) {
    __shared__ float ws[64 * 9];
    const float* in = (in_sel == 0) ? ext_in : (in_sel == 1 ? g_cb1 : g_cb2);
    float* out = (out_sel == 1) ? g_cb1 : g_cb2;
    int oc = blockIdx.y;
    for (int idx = threadIdx.x; idx < IC * 9; idx += 256) ws[idx] = w[oc * IC * 9 + idx];
    __syncthreads();
    int p = blockIdx.x * 256 + threadIdx.x;
    int y = p >> 6, xx = p & 63;
    float acc = b[oc];
    for (int ic = 0; ic < IC; ic++) {
        const float* ip = in + ic * 4096;
        const float* wp = ws + ic * 9;
#pragma unroll
        for (int ky = 0; ky < 3; ky++) {
            int iy = y + ky - 1;
            if ((unsigned)iy >= 64u) continue;
#pragma unroll
            for (int kx = 0; kx < 3; kx++) {
                int ix = xx + kx - 1;
                if ((unsigned)ix >= 64u) continue;
                acc += ip[iy * 64 + ix] * wp[ky * 3 + kx];
            }
        }
    }
    out[oc * 4096 + p] = selu_f(acc);
}

__global__ void avgpool_k() {
    __shared__ float red[256];
    int c = blockIdx.x;
    float s = 0.f;
    for (int p = threadIdx.x; p < 4096; p += 256) s += g_cb2[c * 4096 + p];
    red[threadIdx.x] = s;
    __syncthreads();
    for (int o = 128; o > 0; o >>= 1) {
        if (threadIdx.x < o) red[threadIdx.x] += red[threadIdx.x + o];
        __syncthreads();
    }
    if (threadIdx.x == 0) g_gf[c] = red[0] * (1.f / 4096.f);
}

// layer-1 input (fp16, Kp=48 padded) + boundary flags
__global__ void build_in_k(const float* __restrict__ x) {
    int i = blockIdx.x * 256 + threadIdx.x;
    if (i >= NN) return;
    float x0 = x[i * 10], x1 = x[i * 10 + 1];
    unsigned char f = 0;
    if (x0 == 1.f) f |= 1;
    if (x0 == 0.f) f |= 2;
    if (x1 == 0.f) f |= 4;
    if (x1 == 1.f) f |= 8;
    g_bflags[i] = f;
    __half* row = g_feath + i * 48;
#pragma unroll
    for (int c = 0; c < 24; c++) row[c] = __float2half(g_gf[c]);
#pragma unroll
    for (int c = 0; c < 10; c++) row[24 + c] = __float2half(x[i * 10 + c]);
#pragma unroll
    for (int c = 34; c < 48; c++) row[c] = __float2half(0.f);
}

// ---------------- weight conversion: W[K][HC] fp32 -> g_wh[HC][Kp] fp16 ----------------
__global__ void wconv_k(const float* __restrict__ W, int K, int HC, int Kp) {
    int idx = blockIdx.x * 256 + threadIdx.x;
    if (idx >= HC * Kp) return;
    int n = idx / Kp, kp = idx - n * Kp;
    float f = (kp < K) ? W[(size_t)kp * HC + n] : 0.f;
    g_wh[idx] = __float2half(f);
}

// ---------------- fp16 tensor-core GEMM: g_hbufh[N,M] = g_feath[N,Kp] @ g_wh[:,Kp]^T ----------------
__device__ __forceinline__ void mma_f16(float& c0, float& c1, float& c2, float& c3,
                                        uint32_t a0, uint32_t a1, uint32_t a2, uint32_t a3,
                                        uint32_t b0, uint32_t b1) {
    asm volatile(
        "mma.sync.aligned.m16n8k16.row.col.f32.f16.f16.f32 "
        "{%0,%1,%2,%3}, {%4,%5,%6,%7}, {%8,%9}, {%0,%1,%2,%3};"
        : "+f"(c0), "+f"(c1), "+f"(c2), "+f"(c3)
        : "r"(a0), "r"(a1), "r"(a2), "r"(a3), "r"(b0), "r"(b1));
}

__global__ void __launch_bounds__(256) hgemm_k(int Kp, int M) {
    // Block 128(M) x 64(N); 8 warps 4(M) x 2(N); warp tile 32x32 via m16n8k16.
    __shared__ alignas(16) __half As[128][24];   // [m][k], stride 24 halfs: frag reads conflict-free
    __shared__ alignas(16) __half Bs[64][24];    // [n][k]

    const int tid = threadIdx.x;
    const int wid = tid >> 5, lane = tid & 31;
    const int group = lane >> 2, tig = lane & 3;
    const int warpM = wid & 3, warpN = wid >> 2;
    const int row0 = blockIdx.y * 128, col0 = blockIdx.x * 64;

    float acc[2][4][4];
#pragma unroll
    for (int mf = 0; mf < 2; mf++)
#pragma unroll
        for (int nf = 0; nf < 4; nf++)
#pragma unroll
            for (int r = 0; r < 4; r++) acc[mf][nf][r] = 0.f;

    const int ntiles = Kp >> 4;
    for (int kt = 0; kt < ntiles; kt++) {
        int k0 = kt << 4;
        // stage A: 128 rows x 16 halfs (one uint4 = 8 halfs per thread)
        {
            int r = tid >> 1, q = tid & 1;
            int gr = row0 + r;
            uint4 v = make_uint4(0, 0, 0, 0);
            if (gr < NN) v = *(const uint4*)&g_feath[(size_t)gr * Kp + k0 + q * 8];
            *(uint4*)&As[r][q * 8] = v;
        }
        // stage B: 64 n x 16 halfs
        if (tid < 128) {
            int n = tid >> 1, q = tid & 1;
            uint4 v = make_uint4(0, 0, 0, 0);
            if (col0 + n < M) v = *(const uint4*)&g_wh[(size_t)(col0 + n) * Kp + k0 + q * 8];
            *(uint4*)&Bs[n][q * 8] = v;
        }
        __syncthreads();

        uint32_t a[2][4], b[4][2];
#pragma unroll
        for (int mf = 0; mf < 2; mf++) {
            int mr = warpM * 32 + mf * 16 + group;
            a[mf][0] = *(const uint32_t*)&As[mr][2 * tig];
            a[mf][1] = *(const uint32_t*)&As[mr + 8][2 * tig];
            a[mf][2] = *(const uint32_t*)&As[mr][2 * tig + 8];
            a[mf][3] = *(const uint32_t*)&As[mr + 8][2 * tig + 8];
        }
#pragma unroll
        for (int nf = 0; nf < 4; nf++) {
            int nr = warpN * 32 + nf * 8 + group;
            b[nf][0] = *(const uint32_t*)&Bs[nr][2 * tig];
            b[nf][1] = *(const uint32_t*)&Bs[nr][2 * tig + 8];
        }
#pragma unroll
        for (int mf = 0; mf < 2; mf++)
#pragma unroll
            for (int nf = 0; nf < 4; nf++) {
                float* c = acc[mf][nf];
                mma_f16(c[0], c[1], c[2], c[3],
                        a[mf][0], a[mf][1], a[mf][2], a[mf][3], b[nf][0], b[nf][1]);
            }
        __syncthreads();
    }

    // epilogue: c0/c1 -> (row=group, cols 2tig..); c2/c3 -> row=group+8; store fp16
#pragma unroll
    for (int mf = 0; mf < 2; mf++) {
        int rbase = row0 + warpM * 32 + mf * 16 + group;
#pragma unroll
        for (int nf = 0; nf < 4; nf++) {
            int cbase = col0 + warpN * 32 + nf * 8 + 2 * tig;
            if (cbase < M) {
                if (rbase < NN) {
                    __half2 h = __floats2half2_rn(acc[mf][nf][0], acc[mf][nf][1]);
                    *(__half2*)&g_hbufh[(size_t)rbase * M + cbase] = h;
                }
                if (rbase + 8 < NN) {
                    __half2 h = __floats2half2_rn(acc[mf][nf][2], acc[mf][nf][3]);
                    *(__half2*)&g_hbufh[(size_t)(rbase + 8) * M + cbase] = h;
                }
            }
        }
    }
}

// ---------------- per-node attention dots hs/hd (reads g_hbufh) ----------------
__global__ void attn_dots_k(const float* __restrict__ as_, const float* __restrict__ ad_,
                            int H, int C) {
    int i = blockIdx.x;
    int warp = threadIdx.x >> 5, lane = threadIdx.x & 31;
    const __half2* hrow = (const __half2*)(g_hbufh + (size_t)i * H * C);
    int C2 = C >> 1;
    for (int hh = warp; hh < H; hh += 8) {
        float ps = 0.f, pd = 0.f;
        for (int c2 = lane; c2 < C2; c2 += 32) {
            float2 f = __half22float2(hrow[hh * C2 + c2]);
            int c = 2 * c2;
            ps += f.x * as_[hh * C + c] + f.y * as_[hh * C + c + 1];
            pd += f.x * ad_[hh * C + c] + f.y * ad_[hh * C + c + 1];
        }
#pragma unroll
        for (int o = 16; o; o >>= 1) {
            ps += __shfl_xor_sync(0xffffffffu, ps, o);
            pd += __shfl_xor_sync(0xffffffffu, pd, o);
        }
        if (lane == 0) { g_hs[i * H + hh] = ps; g_hd[i * H + hh] = pd; }
    }
}

// ---------------- GAT aggregation (vectorized fp16 gather) ----------------
// One block per dst. VW halfs per thread per edge row. KPN = next layer's padded stride (==C).
template <int H, int C, int VW, bool FINAL>
__global__ void gat_agg_k(const float* __restrict__ bias, const float* __restrict__ x,
                          float* __restrict__ outp) {
    constexpr int HC = H * C;
    constexpr int NT = 256;
    constexpr int NV = HC / VW;
    constexpr int CH = 32;
    static_assert(NV <= NT, "vector coverage");
    __shared__ float s_m[H], s_z[H], s_hdi[H];
    __shared__ int   s_src[CH];
    __shared__ float s_e[CH * H];
    __shared__ float s_agg[HC];

    int i = blockIdx.x;
    int tid = threadIdx.x;
    int e0 = g_off[i];
    int deg = g_off[i + 1] - e0;
    if (tid < H) s_hdi[tid] = g_hd[i * H + tid];
    __syncthreads();

    // Pass A: online softmax stats per head
    float m_run = -1e30f, z_run = 0.f;
    for (int c0 = 0; c0 < deg; c0 += CH) {
        int cl = min(CH, deg - c0);
        if (tid < cl) s_src[tid] = g_csr[e0 + c0 + tid];
        __syncthreads();
        for (int idx = tid; idx < cl * H; idx += NT) {
            int ce = idx / H, hh = idx - ce * H;
            float v = g_hs[s_src[ce] * H + hh] + s_hdi[hh];
            s_e[idx] = v > 0.f ? v : 0.2f * v;
        }
        __syncthreads();
        if (tid < H) {
            for (int ce = 0; ce < cl; ce++) {
                float v = s_e[ce * H + tid];
                float mn = fmaxf(m_run, v);
                z_run = z_run * expf(m_run - mn) + expf(v - mn);
                m_run = mn;
            }
        }
        __syncthreads();
    }
    if (tid < H) { s_m[tid] = m_run; s_z[tid] = z_run; }
    __syncthreads();

    // Pass B: alpha-weighted vectorized gather of h[src]
    float acc[VW];
#pragma unroll
    for (int v = 0; v < VW; v++) acc[v] = 0.f;
    const int hh_t = (tid * VW) / C;

    for (int c0 = 0; c0 < deg; c0 += CH) {
        int cl = min(CH, deg - c0);
        if (tid < cl) s_src[tid] = g_csr[e0 + c0 + tid];
        __syncthreads();
        for (int idx = tid; idx < cl * H; idx += NT) {
            int ce = idx / H, hh = idx - ce * H;
            float v = g_hs[s_src[ce] * H + hh] + s_hdi[hh];
            v = v > 0.f ? v : 0.2f * v;
            s_e[idx] = expf(v - s_m[hh]) / (s_z[hh] + 1e-16f);
        }
        __syncthreads();
        if (tid < NV) {
            for (int ce = 0; ce < cl; ce++) {
                const __half* hrow = g_hbufh + (size_t)s_src[ce] * HC + tid * VW;
                float al = s_e[ce * H + hh_t];
                if (VW == 8) {
                    uint4 pk = *(const uint4*)hrow;
                    float2 f0 = __half22float2(*(__half2*)&pk.x);
                    float2 f1 = __half22float2(*(__half2*)&pk.y);
                    float2 f2 = __half22float2(*(__half2*)&pk.z);
                    float2 f3 = __half22float2(*(__half2*)&pk.w);
                    acc[0] += al * f0.x; acc[1] += al * f0.y;
                    acc[2] += al * f1.x; acc[3] += al * f1.y;
                    acc[4] += al * f2.x; acc[5] += al * f2.y;
                    acc[6] += al * f3.x; acc[7] += al * f3.y;
                } else if (VW == 4) {
                    uint2 pk = *(const uint2*)hrow;
                    float2 f0 = __half22float2(*(__half2*)&pk.x);
                    float2 f1 = __half22float2(*(__half2*)&pk.y);
                    acc[0] += al * f0.x; acc[1] += al * f0.y;
                    acc[2] += al * f1.x; acc[3] += al * f1.y;
                } else {
                    float2 f0 = __half22float2(*(const __half2*)hrow);
                    acc[0] += al * f0.x; acc[1] += al * f0.y;
                }
            }
        }
        __syncthreads();
    }

    if (tid < NV) {
#pragma unroll
        for (int v = 0; v < VW; v++) s_agg[tid * VW + v] = acc[v];
    }
    __syncthreads();

    unsigned char f = g_bflags[i];
    for (int c = tid; c < C; c += NT) {
        float v = 0.f;
#pragma unroll
        for (int hh = 0; hh < H; hh++) v += s_agg[hh * C + c];
        v = v * (1.f / H) + bias[c];
        v = selu_f(v);
        if (FINAL) v += x[i * 10 + c];
        if (c == 0)      v = (f & 2) ? 0.f : ((f & 1) ? 1.f : v);
        else if (c == 1) v = (f & 8) ? 1.f : ((f & 4) ? 0.f : v);
        if (FINAL) outp[(size_t)i * C + c] = v;
        else       g_feath[(size_t)i * C + c] = __float2half(v);
    }
}

// ---------------- host launch ----------------
extern "C" void kernel_launch(void* const* d_in, const int* in_sizes, int n_in,
                              void* d_out, int out_size) {
    const float* x  = (const float*)d_in[0];
    const void*  ei = d_in[1];
    const float* cf = (const float*)d_in[2];
    const float* cw[4]  = {(const float*)d_in[3], (const float*)d_in[5],
                           (const float*)d_in[7], (const float*)d_in[9]};
    const float* cbi[4] = {(const float*)d_in[4], (const float*)d_in[6],
                           (const float*)d_in[8], (const float*)d_in[10]};
    const float *gw[5], *gas[5], *gad[5], *gb[5];
    for (int l = 0; l < 5; l++) {
        gw[l]  = (const float*)d_in[11 + 4 * l];
        gas[l] = (const float*)d_in[12 + 4 * l];
        gad[l] = (const float*)d_in[13 + 4 * l];
        gb[l]  = (const float*)d_in[14 + 4 * l];
    }
    float* out = (float*)d_out;

    init_detect_k<<<(NN + 255) / 256, 256>>>(ei);
    csr_count_k<<<(NE + 255) / 256, 256>>>(ei);
    csr_scan_k<<<1, 1024>>>();
    csr_fill_k<<<(ET + 255) / 256, 256>>>(ei);

    conv3x3_k<<<dim3(16, 16), 256>>>(cf, 0, 1, cw[0], cbi[0], 4);
    conv3x3_k<<<dim3(16, 32), 256>>>(nullptr, 1, 2, cw[1], cbi[1], 16);
    conv3x3_k<<<dim3(16, 64), 256>>>(nullptr, 2, 1, cw[2], cbi[2], 32);
    conv3x3_k<<<dim3(16, 24), 256>>>(nullptr, 1, 2, cw[3], cbi[3], 64);
    avgpool_k<<<24, 256>>>();
    build_in_k<<<(NN + 255) / 256, 256>>>(x);

    const int fins[5] = {34, 64, 128, 256, 128};
    const int Kps[5]  = {48, 64, 128, 256, 128};
    const int Hs[5]   = {8, 16, 8, 8, 16};
    const int Cs[5]   = {64, 128, 256, 128, 2};

    for (int l = 0; l < 5; l++) {
        int HC = Hs[l] * Cs[l];
        int Kp = Kps[l];
        wconv_k<<<(HC * Kp + 255) / 256, 256>>>(gw[l], fins[l], HC, Kp);
        dim3 gg((HC + 63) / 64, (NN + 127) / 128);
        hgemm_k<<<gg, 256>>>(Kp, HC);
        attn_dots_k<<<NN, 256>>>(gas[l], gad[l], Hs[l], Cs[l]);
        switch (l) {
            case 0: gat_agg_k<8, 64, 2, false><<<NN, 256>>>(gb[0], x, nullptr); break;
            case 1: gat_agg_k<16, 128, 8, false><<<NN, 256>>>(gb[1], x, nullptr); break;
            case 2: gat_agg_k<8, 256, 8, false><<<NN, 256>>>(gb[2], x, nullptr); break;
            case 3: gat_agg_k<8, 128, 4, false><<<NN, 256>>>(gb[3], x, nullptr); break;
            case 4: gat_agg_k<16, 2, 2, true><<<NN, 256>>>(gb[4], x, out); break;
        }
    }
}

// round 15
// speedup vs baseline: 1.4654x; 1.4654x over previous
#include <cuda_runtime.h>
#include <cuda_fp16.h>
#include <math.h>
#include <stdint.h>

#define NN 10000
#define NE 160000
#define ET (NN + NE)

// ---------------- scratch (device globals; referenced by symbol ONLY in device code) ----------------
__device__ __half g_feath[NN * 256];    // layer input features fp16 (row-major, stride = Kp)
__device__ __half g_wh[2048 * 256];     // W^T fp16, [HC][Kp] K-major
__device__ __half g_hbufh[NN * 2048];   // h = X @ W  fp16 (row-major, stride = H*C)
__device__ float  g_hs[NN * 16];
__device__ float  g_hd[NN * 16];
__device__ int    g_cnt[NN];
__device__ int    g_cur[NN];
__device__ int    g_off[NN + 1];
__device__ int    g_csr[ET];
__device__ float  g_cb1[64 * 64 * 64];
__device__ float  g_cb2[64 * 64 * 64];
__device__ float  g_gf[24];
__device__ unsigned char g_bflags[NN];
__device__ int    g_is64;

__device__ __forceinline__ float selu_f(float v) {
    const float sc = 1.0507009873554805f;
    const float al = 1.6732632423543772f;
    return v > 0.f ? sc * v : sc * al * (expf(v) - 1.f);
}

__device__ __forceinline__ int edge_at(const void* ei, int idx) {
    if (g_is64) return (int)((const long long*)ei)[idx];
    return ((const int*)ei)[idx];
}

// ---------------- CSR init + dtype detection ----------------
__global__ void init_detect_k(const void* __restrict__ ei) {
    int i = blockIdx.x * 256 + threadIdx.x;
    if (i < NN) { g_cnt[i] = 1; g_cur[i] = 0; }
    if (blockIdx.x == 0) {
        __shared__ int nz;
        if (threadIdx.x == 0) nz = 0;
        __syncthreads();
        const int* p = (const int*)ei;
        int found = 0;
        for (int j = threadIdx.x; j < 4096; j += 256)
            if (p[2 * j + 1] != 0) found = 1;
        if (found) atomicOr(&nz, 1);
        __syncthreads();
        if (threadIdx.x == 0) g_is64 = nz ? 0 : 1;
    }
}

__global__ void csr_count_k(const void* __restrict__ ei) {
    int e = blockIdx.x * 256 + threadIdx.x;
    if (e < NE) atomicAdd(&g_cnt[edge_at(ei, NE + e)], 1);
}

__global__ void csr_scan_k() {
    __shared__ int wsum[32];
    int tid = threadIdx.x;
    const int per = 10;
    int start = tid * per;
    int s = 0;
#pragma unroll
    for (int j = 0; j < per; j++) { int idx = start + j; if (idx < NN) s += g_cnt[idx]; }
    int lane = tid & 31, warp = tid >> 5;
    int v = s;
#pragma unroll
    for (int o = 1; o < 32; o <<= 1) {
        int t = __shfl_up_sync(0xffffffffu, v, o);
        if (lane >= o) v += t;
    }
    if (lane == 31) wsum[warp] = v;
    __syncthreads();
    if (warp == 0) {
        int w = wsum[lane];
#pragma unroll
        for (int o = 1; o < 32; o <<= 1) {
            int t = __shfl_up_sync(0xffffffffu, w, o);
            if (lane >= o) w += t;
        }
        wsum[lane] = w;
    }
    __syncthreads();
    int base = (warp ? wsum[warp - 1] : 0) + (v - s);
    int run = base;
#pragma unroll
    for (int j = 0; j < per; j++) {
        int idx = start + j;
        if (idx < NN) { g_off[idx] = run; run += g_cnt[idx]; }
    }
    if (tid == 0) g_off[NN] = wsum[31];
}

__global__ void csr_fill_k(const void* __restrict__ ei) {
    int idx = blockIdx.x * 256 + threadIdx.x;
    if (idx >= ET) return;
    int s, d;
    if (idx < NN) { s = idx; d = idx; }
    else {
        int e = idx - NN;
        s = edge_at(ei, e);
        d = edge_at(ei, NE + e);
    }
    int pos = g_off[d] + atomicAdd(&g_cur[d], 1);
    g_csr[pos] = s;
}

// ---------------- CNN ----------------
__global__ void conv3x3_k(const float* __restrict__ ext_in, int in_sel, int out_sel,
                          const float* __restrict__ w, const float* __restrict__ b, int IC) {
    __shared__ float ws[64 * 9];
    const float* in = (in_sel == 0) ? ext_in : (in_sel == 1 ? g_cb1 : g_cb2);
    float* out = (out_sel == 1) ? g_cb1 : g_cb2;
    int oc = blockIdx.y;
    for (int idx = threadIdx.x; idx < IC * 9; idx += 256) ws[idx] = w[oc * IC * 9 + idx];
    __syncthreads();
    int p = blockIdx.x * 256 + threadIdx.x;
    int y = p >> 6, xx = p & 63;
    float acc = b[oc];
    for (int ic = 0; ic < IC; ic++) {
        const float* ip = in + ic * 4096;
        const float* wp = ws + ic * 9;
#pragma unroll
        for (int ky = 0; ky < 3; ky++) {
            int iy = y + ky - 1;
            if ((unsigned)iy >= 64u) continue;
#pragma unroll
            for (int kx = 0; kx < 3; kx++) {
                int ix = xx + kx - 1;
                if ((unsigned)ix >= 64u) continue;
                acc += ip[iy * 64 + ix] * wp[ky * 3 + kx];
            }
        }
    }
    out[oc * 4096 + p] = selu_f(acc);
}

__global__ void avgpool_k() {
    __shared__ float red[256];
    int c = blockIdx.x;
    float s = 0.f;
    for (int p = threadIdx.x; p < 4096; p += 256) s += g_cb2[c * 4096 + p];
    red[threadIdx.x] = s;
    __syncthreads();
    for (int o = 128; o > 0; o >>= 1) {
        if (threadIdx.x < o) red[threadIdx.x] += red[threadIdx.x + o];
        __syncthreads();
    }
    if (threadIdx.x == 0) g_gf[c] = red[0] * (1.f / 4096.f);
}

// layer-1 input (fp16, Kp=64 padded) + boundary flags
__global__ void build_in_k(const float* __restrict__ x) {
    int i = blockIdx.x * 256 + threadIdx.x;
    if (i >= NN) return;
    float x0 = x[i * 10], x1 = x[i * 10 + 1];
    unsigned char f = 0;
    if (x0 == 1.f) f |= 1;
    if (x0 == 0.f) f |= 2;
    if (x1 == 0.f) f |= 4;
    if (x1 == 1.f) f |= 8;
    g_bflags[i] = f;
    __half* row = g_feath + i * 64;
#pragma unroll
    for (int c = 0; c < 24; c++) row[c] = __float2half(g_gf[c]);
#pragma unroll
    for (int c = 0; c < 10; c++) row[24 + c] = __float2half(x[i * 10 + c]);
#pragma unroll
    for (int c = 34; c < 64; c++) row[c] = __float2half(0.f);
}

// ---------------- weight conversion: W[K][HC] fp32 -> g_wh[HC][Kp] fp16 ----------------
__global__ void wconv_k(const float* __restrict__ W, int K, int HC, int Kp) {
    int idx = blockIdx.x * 256 + threadIdx.x;
    if (idx >= HC * Kp) return;
    int n = idx / Kp, kp = idx - n * Kp;
    float f = (kp < K) ? W[(size_t)kp * HC + n] : 0.f;
    g_wh[idx] = __float2half(f);
}

// ---------------- fp16 tensor-core GEMM v2: double-buffered, K-tile 32 ----------------
__device__ __forceinline__ void mma_f16(float& c0, float& c1, float& c2, float& c3,
                                        uint32_t a0, uint32_t a1, uint32_t a2, uint32_t a3,
                                        uint32_t b0, uint32_t b1) {
    asm volatile(
        "mma.sync.aligned.m16n8k16.row.col.f32.f16.f16.f32 "
        "{%0,%1,%2,%3}, {%4,%5,%6,%7}, {%8,%9}, {%0,%1,%2,%3};"
        : "+f"(c0), "+f"(c1), "+f"(c2), "+f"(c3)
        : "r"(a0), "r"(a1), "r"(a2), "r"(a3), "r"(b0), "r"(b1));
}

__global__ void __launch_bounds__(256) hgemm_k(int Kp, int M) {
    // Block 128(M) x 64(N); 8 warps 4(M) x 2(N); warp tile 32x32; BK=32, double-buffered.
    __shared__ alignas(16) __half As[2][128][40];   // [m][k], stride 40: frag reads conflict-free
    __shared__ alignas(16) __half Bs[2][64][40];    // [n][k]

    const int tid = threadIdx.x;
    const int wid = tid >> 5, lane = tid & 31;
    const int group = lane >> 2, tig = lane & 3;
    const int warpM = wid & 3, warpN = wid >> 2;
    const int row0 = blockIdx.y * 128, col0 = blockIdx.x * 64;

    float acc[2][4][4];
#pragma unroll
    for (int mf = 0; mf < 2; mf++)
#pragma unroll
        for (int nf = 0; nf < 4; nf++)
#pragma unroll
            for (int r = 0; r < 4; r++) acc[mf][nf][r] = 0.f;

    const int aq = tid & 3;          // which uint4 (8 halfs) within the 32-half row chunk
    const int br = tid >> 2;         // B row 0..63

    uint4 raA[2], raB;
    auto gload = [&](int kt) {
        int k0 = kt * 32;
#pragma unroll
        for (int p = 0; p < 2; p++) {
            int r = (tid + p * 256) >> 2;        // p0: rows 0..63, p1: rows 64..127
            int gr = row0 + r;
            raA[p] = make_uint4(0, 0, 0, 0);
            if (gr < NN) raA[p] = *(const uint4*)&g_feath[(size_t)gr * Kp + k0 + aq * 8];
        }
        raB = make_uint4(0, 0, 0, 0);
        if (col0 + br < M) raB = *(const uint4*)&g_wh[(size_t)(col0 + br) * Kp + k0 + aq * 8];
    };
    auto sstore = [&](int buf) {
#pragma unroll
        for (int p = 0; p < 2; p++) {
            int r = (tid + p * 256) >> 2;
            *(uint4*)&As[buf][r][aq * 8] = raA[p];
        }
        *(uint4*)&Bs[buf][br][aq * 8] = raB;
    };

    const int ntiles = Kp >> 5;
    gload(0);
    sstore(0);
    __syncthreads();

    for (int kt = 0; kt < ntiles; kt++) {
        int buf = kt & 1;
        bool more = (kt + 1 < ntiles);
        if (more) gload(kt + 1);
#pragma unroll
        for (int ks = 0; ks < 2; ks++) {
            int kb = ks * 16 + 2 * tig;
            uint32_t a[2][4], b[4][2];
#pragma unroll
            for (int mf = 0; mf < 2; mf++) {
                int mr = warpM * 32 + mf * 16 + group;
                a[mf][0] = *(const uint32_t*)&As[buf][mr][kb];
                a[mf][1] = *(const uint32_t*)&As[buf][mr + 8][kb];
                a[mf][2] = *(const uint32_t*)&As[buf][mr][kb + 8];
                a[mf][3] = *(const uint32_t*)&As[buf][mr + 8][kb + 8];
            }
#pragma unroll
            for (int nf = 0; nf < 4; nf++) {
                int nr = warpN * 32 + nf * 8 + group;
                b[nf][0] = *(const uint32_t*)&Bs[buf][nr][kb];
                b[nf][1] = *(const uint32_t*)&Bs[buf][nr][kb + 8];
            }
#pragma unroll
            for (int mf = 0; mf < 2; mf++)
#pragma unroll
                for (int nf = 0; nf < 4; nf++) {
                    float* c = acc[mf][nf];
                    mma_f16(c[0], c[1], c[2], c[3],
                            a[mf][0], a[mf][1], a[mf][2], a[mf][3], b[nf][0], b[nf][1]);
                }
        }
        if (more) sstore(buf ^ 1);
        __syncthreads();
    }

    // epilogue: c0/c1 -> (row=group, cols 2tig..); c2/c3 -> row=group+8; store fp16
#pragma unroll
    for (int mf = 0; mf < 2; mf++) {
        int rbase = row0 + warpM * 32 + mf * 16 + group;
#pragma unroll
        for (int nf = 0; nf < 4; nf++) {
            int cbase = col0 + warpN * 32 + nf * 8 + 2 * tig;
            if (cbase < M) {
                if (rbase < NN) {
                    __half2 h = __floats2half2_rn(acc[mf][nf][0], acc[mf][nf][1]);
                    *(__half2*)&g_hbufh[(size_t)rbase * M + cbase] = h;
                }
                if (rbase + 8 < NN) {
                    __half2 h = __floats2half2_rn(acc[mf][nf][2], acc[mf][nf][3]);
                    *(__half2*)&g_hbufh[(size_t)(rbase + 8) * M + cbase] = h;
                }
            }
        }
    }
}

// ---------------- per-node attention dots hs/hd (reads g_hbufh) ----------------
__global__ void attn_dots_k(const float* __restrict__ as_, const float* __restrict__ ad_,
                            int H, int C) {
    int i = blockIdx.x;
    int warp = threadIdx.x >> 5, lane = threadIdx.x & 31;
    const __half2* hrow = (const __half2*)(g_hbufh + (size_t)i * H * C);
    int C2 = C >> 1;
    for (int hh = warp; hh < H; hh += 8) {
        float ps = 0.f, pd = 0.f;
        for (int c2 = lane; c2 < C2; c2 += 32) {
            float2 f = __half22float2(hrow[hh * C2 + c2]);
            int c = 2 * c2;
            ps += f.x * as_[hh * C + c] + f.y * as_[hh * C + c + 1];
            pd += f.x * ad_[hh * C + c] + f.y * ad_[hh * C + c + 1];
        }
#pragma unroll
        for (int o = 16; o; o >>= 1) {
            ps += __shfl_xor_sync(0xffffffffu, ps, o);
            pd += __shfl_xor_sync(0xffffffffu, pd, o);
        }
        if (lane == 0) { g_hs[i * H + hh] = ps; g_hd[i * H + hh] = pd; }
    }
}

// ---------------- GAT aggregation (vectorized fp16 gather) ----------------
template <int H, int C, int VW, bool FINAL>
__global__ void gat_agg_k(const float* __restrict__ bias, const float* __restrict__ x,
                          float* __restrict__ outp) {
    constexpr int HC = H * C;
    constexpr int NT = 256;
    constexpr int NV = HC / VW;
    constexpr int CH = 32;
    static_assert(NV <= NT, "vector coverage");
    __shared__ float s_m[H], s_z[H], s_hdi[H];
    __shared__ int   s_src[CH];
    __shared__ float s_e[CH * H];
    __shared__ float s_agg[HC];

    int i = blockIdx.x;
    int tid = threadIdx.x;
    int e0 = g_off[i];
    int deg = g_off[i + 1] - e0;
    if (tid < H) s_hdi[tid] = g_hd[i * H + tid];
    __syncthreads();

    // Pass A: online softmax stats per head
    float m_run = -1e30f, z_run = 0.f;
    for (int c0 = 0; c0 < deg; c0 += CH) {
        int cl = min(CH, deg - c0);
        if (tid < cl) s_src[tid] = g_csr[e0 + c0 + tid];
        __syncthreads();
        for (int idx = tid; idx < cl * H; idx += NT) {
            int ce = idx / H, hh = idx - ce * H;
            float v = g_hs[s_src[ce] * H + hh] + s_hdi[hh];
            s_e[idx] = v > 0.f ? v : 0.2f * v;
        }
        __syncthreads();
        if (tid < H) {
            for (int ce = 0; ce < cl; ce++) {
                float v = s_e[ce * H + tid];
                float mn = fmaxf(m_run, v);
                z_run = z_run * expf(m_run - mn) + expf(v - mn);
                m_run = mn;
            }
        }
        __syncthreads();
    }
    if (tid < H) { s_m[tid] = m_run; s_z[tid] = z_run; }
    __syncthreads();

    // Pass B: alpha-weighted vectorized gather of h[src]
    float acc[VW];
#pragma unroll
    for (int v = 0; v < VW; v++) acc[v] = 0.f;
    const int hh_t = (tid * VW) / C;

    for (int c0 = 0; c0 < deg; c0 += CH) {
        int cl = min(CH, deg - c0);
        if (tid < cl) s_src[tid] = g_csr[e0 + c0 + tid];
        __syncthreads();
        for (int idx = tid; idx < cl * H; idx += NT) {
            int ce = idx / H, hh = idx - ce * H;
            float v = g_hs[s_src[ce] * H + hh] + s_hdi[hh];
            v = v > 0.f ? v : 0.2f * v;
            s_e[idx] = expf(v - s_m[hh]) / (s_z[hh] + 1e-16f);
        }
        __syncthreads();
        if (tid < NV) {
            for (int ce = 0; ce < cl; ce++) {
                const __half* hrow = g_hbufh + (size_t)s_src[ce] * HC + tid * VW;
                float al = s_e[ce * H + hh_t];
                if (VW == 8) {
                    uint4 pk = *(const uint4*)hrow;
                    float2 f0 = __half22float2(*(__half2*)&pk.x);
                    float2 f1 = __half22float2(*(__half2*)&pk.y);
                    float2 f2 = __half22float2(*(__half2*)&pk.z);
                    float2 f3 = __half22float2(*(__half2*)&pk.w);
                    acc[0] += al * f0.x; acc[1] += al * f0.y;
                    acc[2] += al * f1.x; acc[3] += al * f1.y;
                    acc[4] += al * f2.x; acc[5] += al * f2.y;
                    acc[6] += al * f3.x; acc[7] += al * f3.y;
                } else if (VW == 4) {
                    uint2 pk = *(const uint2*)hrow;
                    float2 f0 = __half22float2(*(__half2*)&pk.x);
                    float2 f1 = __half22float2(*(__half2*)&pk.y);
                    acc[0] += al * f0.x; acc[1] += al * f0.y;
                    acc[2] += al * f1.x; acc[3] += al * f1.y;
                } else {
                    float2 f0 = __half22float2(*(const __half2*)hrow);
                    acc[0] += al * f0.x; acc[1] += al * f0.y;
                }
            }
        }
        __syncthreads();
    }

    if (tid < NV) {
#pragma unroll
        for (int v = 0; v < VW; v++) s_agg[tid * VW + v] = acc[v];
    }
    __syncthreads();

    unsigned char f = g_bflags[i];
    for (int c = tid; c < C; c += NT) {
        float v = 0.f;
#pragma unroll
        for (int hh = 0; hh < H; hh++) v += s_agg[hh * C + c];
        v = v * (1.f / H) + bias[c];
        v = selu_f(v);
        if (FINAL) v += x[i * 10 + c];
        if (c == 0)      v = (f & 2) ? 0.f : ((f & 1) ? 1.f : v);
        else if (c == 1) v = (f & 8) ? 1.f : ((f & 4) ? 0.f : v);
        if (FINAL) outp[(size_t)i * C + c] = v;
        else       g_feath[(size_t)i * C + c] = __float2half(v);
    }
}

// ---------------- host launch ----------------
extern "C" void kernel_launch(void* const* d_in, const int* in_sizes, int n_in,
                              void* d_out, int out_size) {
    const float* x  = (const float*)d_in[0];
    const void*  ei = d_in[1];
    const float* cf = (const float*)d_in[2];
    const float* cw[4]  = {(const float*)d_in[3], (const float*)d_in[5],
                           (const float*)d_in[7], (const float*)d_in[9]};
    const float* cbi[4] = {(const float*)d_in[4], (const float*)d_in[6],
                           (const float*)d_in[8], (const float*)d_in[10]};
    const float *gw[5], *gas[5], *gad[5], *gb[5];
    for (int l = 0; l < 5; l++) {
        gw[l]  = (const float*)d_in[11 + 4 * l];
        gas[l] = (const float*)d_in[12 + 4 * l];
        gad[l] = (const float*)d_in[13 + 4 * l];
        gb[l]  = (const float*)d_in[14 + 4 * l];
    }
    float* out = (float*)d_out;

    init_detect_k<<<(NN + 255) / 256, 256>>>(ei);
    csr_count_k<<<(NE + 255) / 256, 256>>>(ei);
    csr_scan_k<<<1, 1024>>>();
    csr_fill_k<<<(ET + 255) / 256, 256>>>(ei);

    conv3x3_k<<<dim3(16, 16), 256>>>(cf, 0, 1, cw[0], cbi[0], 4);
    conv3x3_k<<<dim3(16, 32), 256>>>(nullptr, 1, 2, cw[1], cbi[1], 16);
    conv3x3_k<<<dim3(16, 64), 256>>>(nullptr, 2, 1, cw[2], cbi[2], 32);
    conv3x3_k<<<dim3(16, 24), 256>>>(nullptr, 1, 2, cw[3], cbi[3], 64);
    avgpool_k<<<24, 256>>>();
    build_in_k<<<(NN + 255) / 256, 256>>>(x);

    const int fins[5] = {34, 64, 128, 256, 128};
    const int Kps[5]  = {64, 64, 128, 256, 128};
    const int Hs[5]   = {8, 16, 8, 8, 16};
    const int Cs[5]   = {64, 128, 256, 128, 2};

    for (int l = 0; l < 5; l++) {
        int HC = Hs[l] * Cs[l];
        int Kp = Kps[l];
        wconv_k<<<(HC * Kp + 255) / 256, 256>>>(gw[l], fins[l], HC, Kp);
        dim3 gg((HC + 63) / 64, (NN + 127) / 128);
        hgemm_k<<<gg, 256>>>(Kp, HC);
        attn_dots_k<<<NN, 256>>>(gas[l], gad[l], Hs[l], Cs[l]);
        switch (l) {
            case 0: gat_agg_k<8, 64, 2, false><<<NN, 256>>>(gb[0], x, nullptr); break;
            case 1: gat_agg_k<16, 128, 8, false><<<NN, 256>>>(gb[1], x, nullptr); break;
            case 2: gat_agg_k<8, 256, 8, false><<<NN, 256>>>(gb[2], x, nullptr); break;
            case 3: gat_agg_k<8, 128, 4, false><<<NN, 256>>>(gb[3], x, nullptr); break;
            case 4: gat_agg_k<16, 2, 2, true><<<NN, 256>>>(gb[4], x, out); break;
        }
    }
}

// round 16
// speedup vs baseline: 1.6043x; 1.0948x over previous
#include <cuda_runtime.h>
#include <cuda_fp16.h>
#include <math.h>
#include <stdint.h>

#define NN 10000
#define NE 160000
#define ET (NN + NE)

// ---------------- scratch (device globals; referenced by symbol ONLY in device code) ----------------
__device__ __half g_feath[NN * 256];    // layer input features fp16 (row-major, stride = Kp)
__device__ __half g_wh[1048576];        // all layers' W^T fp16, [HC][Kp] K-major, packed
__device__ __half g_hbufh[NN * 2048];   // h = X @ W  fp16 (row-major, stride = H*C)
__device__ float  g_hs[NN * 16];
__device__ float  g_hd[NN * 16];
__device__ int    g_cnt[NN];
__device__ int    g_cur[NN];
__device__ int    g_off[NN + 1];
__device__ int    g_csr[ET];
__device__ float  g_cb1[64 * 64 * 64];
__device__ float  g_cb2[64 * 64 * 64];
__device__ float  g_gf[24];
__device__ unsigned char g_bflags[NN];
__device__ int    g_is64;

__device__ __forceinline__ float selu_f(float v) {
    const float sc = 1.0507009873554805f;
    const float al = 1.6732632423543772f;
    return v > 0.f ? sc * v : sc * al * (expf(v) - 1.f);
}

__device__ __forceinline__ int edge_at(const void* ei, int idx) {
    if (g_is64) return (int)((const long long*)ei)[idx];
    return ((const int*)ei)[idx];
}

__device__ __forceinline__ uint32_t smem_u32(const void* p) {
    uint32_t a;
    asm("{ .reg .u64 t; cvta.to.shared.u64 t, %1; cvt.u32.u64 %0, t; }" : "=r"(a) : "l"(p));
    return a;
}

// ---------------- CSR init + dtype detection ----------------
__global__ void init_detect_k(const void* __restrict__ ei) {
    int i = blockIdx.x * 256 + threadIdx.x;
    if (i < NN) { g_cnt[i] = 1; g_cur[i] = 0; }
    if (blockIdx.x == 0) {
        __shared__ int nz;
        if (threadIdx.x == 0) nz = 0;
        __syncthreads();
        const int* p = (const int*)ei;
        int found = 0;
        for (int j = threadIdx.x; j < 4096; j += 256)
            if (p[2 * j + 1] != 0) found = 1;
        if (found) atomicOr(&nz, 1);
        __syncthreads();
        if (threadIdx.x == 0) g_is64 = nz ? 0 : 1;
    }
}

__global__ void csr_count_k(const void* __restrict__ ei) {
    int e = blockIdx.x * 256 + threadIdx.x;
    if (e < NE) atomicAdd(&g_cnt[edge_at(ei, NE + e)], 1);
}

__global__ void csr_scan_k() {
    __shared__ int wsum[32];
    int tid = threadIdx.x;
    const int per = 10;
    int start = tid * per;
    int s = 0;
#pragma unroll
    for (int j = 0; j < per; j++) { int idx = start + j; if (idx < NN) s += g_cnt[idx]; }
    int lane = tid & 31, warp = tid >> 5;
    int v = s;
#pragma unroll
    for (int o = 1; o < 32; o <<= 1) {
        int t = __shfl_up_sync(0xffffffffu, v, o);
        if (lane >= o) v += t;
    }
    if (lane == 31) wsum[warp] = v;
    __syncthreads();
    if (warp == 0) {
        int w = wsum[lane];
#pragma unroll
        for (int o = 1; o < 32; o <<= 1) {
            int t = __shfl_up_sync(0xffffffffu, w, o);
            if (lane >= o) w += t;
        }
        wsum[lane] = w;
    }
    __syncthreads();
    int base = (warp ? wsum[warp - 1] : 0) + (v - s);
    int run = base;
#pragma unroll
    for (int j = 0; j < per; j++) {
        int idx = start + j;
        if (idx < NN) { g_off[idx] = run; run += g_cnt[idx]; }
    }
    if (tid == 0) g_off[NN] = wsum[31];
}

__global__ void csr_fill_k(const void* __restrict__ ei) {
    int idx = blockIdx.x * 256 + threadIdx.x;
    if (idx >= ET) return;
    int s, d;
    if (idx < NN) { s = idx; d = idx; }
    else {
        int e = idx - NN;
        s = edge_at(ei, e);
        d = edge_at(ei, NE + e);
    }
    int pos = g_off[d] + atomicAdd(&g_cur[d], 1);
    g_csr[pos] = s;
}

// ---------------- CNN ----------------
__global__ void conv3x3_k(const float* __restrict__ ext_in, int in_sel, int out_sel,
                          const float* __restrict__ w, const float* __restrict__ b, int IC) {
    __shared__ float ws[64 * 9];
    const float* in = (in_sel == 0) ? ext_in : (in_sel == 1 ? g_cb1 : g_cb2);
    float* out = (out_sel == 1) ? g_cb1 : g_cb2;
    int oc = blockIdx.y;
    for (int idx = threadIdx.x; idx < IC * 9; idx += 256) ws[idx] = w[oc * IC * 9 + idx];
    __syncthreads();
    int p = blockIdx.x * 256 + threadIdx.x;
    int y = p >> 6, xx = p & 63;
    float acc = b[oc];
    for (int ic = 0; ic < IC; ic++) {
        const float* ip = in + ic * 4096;
        const float* wp = ws + ic * 9;
#pragma unroll
        for (int ky = 0; ky < 3; ky++) {
            int iy = y + ky - 1;
            if ((unsigned)iy >= 64u) continue;
#pragma unroll
            for (int kx = 0; kx < 3; kx++) {
                int ix = xx + kx - 1;
                if ((unsigned)ix >= 64u) continue;
                acc += ip[iy * 64 + ix] * wp[ky * 3 + kx];
            }
        }
    }
    out[oc * 4096 + p] = selu_f(acc);
}

__global__ void avgpool_k() {
    __shared__ float red[256];
    int c = blockIdx.x;
    float s = 0.f;
    for (int p = threadIdx.x; p < 4096; p += 256) s += g_cb2[c * 4096 + p];
    red[threadIdx.x] = s;
    __syncthreads();
    for (int o = 128; o > 0; o >>= 1) {
        if (threadIdx.x < o) red[threadIdx.x] += red[threadIdx.x + o];
        __syncthreads();
    }
    if (threadIdx.x == 0) g_gf[c] = red[0] * (1.f / 4096.f);
}

// layer-1 input (fp16, Kp=64 padded) + boundary flags
__global__ void build_in_k(const float* __restrict__ x) {
    int i = blockIdx.x * 256 + threadIdx.x;
    if (i >= NN) return;
    float x0 = x[i * 10], x1 = x[i * 10 + 1];
    unsigned char f = 0;
    if (x0 == 1.f) f |= 1;
    if (x0 == 0.f) f |= 2;
    if (x1 == 0.f) f |= 4;
    if (x1 == 1.f) f |= 8;
    g_bflags[i] = f;
    __half* row = g_feath + i * 64;
#pragma unroll
    for (int c = 0; c < 24; c++) row[c] = __float2half(g_gf[c]);
#pragma unroll
    for (int c = 0; c < 10; c++) row[24 + c] = __float2half(x[i * 10 + c]);
#pragma unroll
    for (int c = 34; c < 64; c++) row[c] = __float2half(0.f);
}

// ---------------- weight conversion: W[K][HC] fp32 -> g_wh[woff + n*Kp + k] fp16 ----------------
__global__ void wconv_k(const float* __restrict__ W, int K, int HC, int Kp, int woff) {
    int idx = blockIdx.x * 256 + threadIdx.x;
    if (idx >= HC * Kp) return;
    int n = idx / Kp, kp = idx - n * Kp;
    float f = (kp < K) ? W[(size_t)kp * HC + n] : 0.f;
    g_wh[woff + idx] = __float2half(f);
}

// ---------------- fp16 tensor-core GEMM v3: double-buffered + ldmatrix ----------------
__device__ __forceinline__ void mma_f16(float& c0, float& c1, float& c2, float& c3,
                                        uint32_t a0, uint32_t a1, uint32_t a2, uint32_t a3,
                                        uint32_t b0, uint32_t b1) {
    asm volatile(
        "mma.sync.aligned.m16n8k16.row.col.f32.f16.f16.f32 "
        "{%0,%1,%2,%3}, {%4,%5,%6,%7}, {%8,%9}, {%0,%1,%2,%3};"
        : "+f"(c0), "+f"(c1), "+f"(c2), "+f"(c3)
        : "r"(a0), "r"(a1), "r"(a2), "r"(a3), "r"(b0), "r"(b1));
}

__device__ __forceinline__ void ldsm4(uint32_t& r0, uint32_t& r1, uint32_t& r2, uint32_t& r3,
                                      uint32_t addr) {
    asm volatile("ldmatrix.sync.aligned.m8n8.x4.shared.b16 {%0,%1,%2,%3}, [%4];"
                 : "=r"(r0), "=r"(r1), "=r"(r2), "=r"(r3) : "r"(addr));
}

__global__ void __launch_bounds__(256) hgemm_k(int Kp, int M, int woff) {
    // Block 128(M) x 64(N); 8 warps 4(M) x 2(N); warp tile 32x32; BK=32, double-buffered.
    __shared__ alignas(16) __half As[2][128][40];   // [m][k], stride 40 halfs (80B): ldmatrix conflict-free
    __shared__ alignas(16) __half Bs[2][64][40];    // [n][k]

    const int tid = threadIdx.x;
    const int wid = tid >> 5, lane = tid & 31;
    const int group = lane >> 2, tig = lane & 3;
    const int warpM = wid & 3, warpN = wid >> 2;
    const int row0 = blockIdx.y * 128, col0 = blockIdx.x * 64;

    float acc[2][4][4];
#pragma unroll
    for (int mf = 0; mf < 2; mf++)
#pragma unroll
        for (int nf = 0; nf < 4; nf++)
#pragma unroll
            for (int r = 0; r < 4; r++) acc[mf][nf][r] = 0.f;

    const int aq = tid & 3;          // which uint4 (8 halfs) within the 32-half row chunk
    const int br = tid >> 2;         // B row 0..63

    // ldmatrix per-lane base offsets (bytes)
    const uint32_t asb = smem_u32(As);
    const uint32_t bsb = smem_u32(Bs);
    constexpr uint32_t ABUF = 128 * 40 * 2;  // 10240 B
    constexpr uint32_t BBUF = 64 * 40 * 2;   // 5120 B
    // A: lane l -> row = warpM*32 + (l&15) (+mf*16), col = (l>>4)*8 (+ks*16)
    const uint32_t aoff = ((uint32_t)(warpM * 32 + (lane & 15)) * 40 + ((lane >> 4) << 3)) * 2;
    // B: lane l -> row = warpN*32 + (l&7) + ((l>>4)&1)*8 (+p*16), col = ((l>>3)&1)*8 (+ks*16)
    const uint32_t boff = ((uint32_t)(warpN * 32 + (lane & 7) + (((lane >> 4) & 1) << 3)) * 40 +
                           (((lane >> 3) & 1) << 3)) * 2;

    uint4 raA[2], raB;
    auto gload = [&](int kt) {
        int k0 = kt * 32;
#pragma unroll
        for (int p = 0; p < 2; p++) {
            int r = (tid + p * 256) >> 2;
            int gr = row0 + r;
            raA[p] = make_uint4(0, 0, 0, 0);
            if (gr < NN) raA[p] = *(const uint4*)&g_feath[(size_t)gr * Kp + k0 + aq * 8];
        }
        raB = make_uint4(0, 0, 0, 0);
        if (col0 + br < M) raB = *(const uint4*)&g_wh[woff + (size_t)(col0 + br) * Kp + k0 + aq * 8];
    };
    auto sstore = [&](int buf) {
#pragma unroll
        for (int p = 0; p < 2; p++) {
            int r = (tid + p * 256) >> 2;
            *(uint4*)&As[buf][r][aq * 8] = raA[p];
        }
        *(uint4*)&Bs[buf][br][aq * 8] = raB;
    };

    const int ntiles = Kp >> 5;
    gload(0);
    sstore(0);
    __syncthreads();

    for (int kt = 0; kt < ntiles; kt++) {
        int buf = kt & 1;
        bool more = (kt + 1 < ntiles);
        if (more) gload(kt + 1);
        uint32_t abase = asb + buf * ABUF + aoff;
        uint32_t bbase = bsb + buf * BBUF + boff;
#pragma unroll
        for (int ks = 0; ks < 2; ks++) {
            uint32_t koffB = (uint32_t)(ks * 16 * 2);  // +16 halfs in k
            uint32_t a0[4], a1[4], b0[4], b1[4];
            ldsm4(a0[0], a0[1], a0[2], a0[3], abase + koffB);                 // mf=0
            ldsm4(a1[0], a1[1], a1[2], a1[3], abase + 16 * 40 * 2 + koffB);   // mf=1
            ldsm4(b0[0], b0[1], b0[2], b0[3], bbase + koffB);                 // nf 0,1
            ldsm4(b1[0], b1[1], b1[2], b1[3], bbase + 16 * 40 * 2 + koffB);   // nf 2,3
            uint32_t* af[2] = {a0, a1};
            uint32_t bf[4][2] = {{b0[0], b0[1]}, {b0[2], b0[3]}, {b1[0], b1[1]}, {b1[2], b1[3]}};
#pragma unroll
            for (int mf = 0; mf < 2; mf++)
#pragma unroll
                for (int nf = 0; nf < 4; nf++) {
                    float* c = acc[mf][nf];
                    mma_f16(c[0], c[1], c[2], c[3],
                            af[mf][0], af[mf][1], af[mf][2], af[mf][3], bf[nf][0], bf[nf][1]);
                }
        }
        if (more) sstore(buf ^ 1);
        __syncthreads();
    }

    // epilogue: c0/c1 -> (row=group, cols 2tig..); c2/c3 -> row=group+8; store fp16
#pragma unroll
    for (int mf = 0; mf < 2; mf++) {
        int rbase = row0 + warpM * 32 + mf * 16 + group;
#pragma unroll
        for (int nf = 0; nf < 4; nf++) {
            int cbase = col0 + warpN * 32 + nf * 8 + 2 * tig;
            if (cbase < M) {
                if (rbase < NN) {
                    __half2 h = __floats2half2_rn(acc[mf][nf][0], acc[mf][nf][1]);
                    *(__half2*)&g_hbufh[(size_t)rbase * M + cbase] = h;
                }
                if (rbase + 8 < NN) {
                    __half2 h = __floats2half2_rn(acc[mf][nf][2], acc[mf][nf][3]);
                    *(__half2*)&g_hbufh[(size_t)(rbase + 8) * M + cbase] = h;
                }
            }
        }
    }
}

// ---------------- per-node attention dots hs/hd (reads g_hbufh) ----------------
__global__ void attn_dots_k(const float* __restrict__ as_, const float* __restrict__ ad_,
                            int H, int C) {
    int i = blockIdx.x;
    int warp = threadIdx.x >> 5, lane = threadIdx.x & 31;
    const __half2* hrow = (const __half2*)(g_hbufh + (size_t)i * H * C);
    int C2 = C >> 1;
    for (int hh = warp; hh < H; hh += 8) {
        float ps = 0.f, pd = 0.f;
        for (int c2 = lane; c2 < C2; c2 += 32) {
            float2 f = __half22float2(hrow[hh * C2 + c2]);
            int c = 2 * c2;
            ps += f.x * as_[hh * C + c] + f.y * as_[hh * C + c + 1];
            pd += f.x * ad_[hh * C + c] + f.y * ad_[hh * C + c + 1];
        }
#pragma unroll
        for (int o = 16; o; o >>= 1) {
            ps += __shfl_xor_sync(0xffffffffu, ps, o);
            pd += __shfl_xor_sync(0xffffffffu, pd, o);
        }
        if (lane == 0) { g_hs[i * H + hh] = ps; g_hd[i * H + hh] = pd; }
    }
}

// ---------------- GAT aggregation (vectorized fp16 gather) ----------------
template <int H, int C, int VW, bool FINAL>
__global__ void gat_agg_k(const float* __restrict__ bias, const float* __restrict__ x,
                          float* __restrict__ outp) {
    constexpr int HC = H * C;
    constexpr int NT = 256;
    constexpr int NV = HC / VW;
    constexpr int CH = 32;
    static_assert(NV <= NT, "vector coverage");
    __shared__ float s_m[H], s_z[H], s_hdi[H];
    __shared__ int   s_src[CH];
    __shared__ float s_e[CH * H];
    __shared__ float s_agg[HC];

    int i = blockIdx.x;
    int tid = threadIdx.x;
    int e0 = g_off[i];
    int deg = g_off[i + 1] - e0;
    if (tid < H) s_hdi[tid] = g_hd[i * H + tid];
    __syncthreads();

    // Pass A: online softmax stats per head
    float m_run = -1e30f, z_run = 0.f;
    for (int c0 = 0; c0 < deg; c0 += CH) {
        int cl = min(CH, deg - c0);
        if (tid < cl) s_src[tid] = g_csr[e0 + c0 + tid];
        __syncthreads();
        for (int idx = tid; idx < cl * H; idx += NT) {
            int ce = idx / H, hh = idx - ce * H;
            float v = g_hs[s_src[ce] * H + hh] + s_hdi[hh];
            s_e[idx] = v > 0.f ? v : 0.2f * v;
        }
        __syncthreads();
        if (tid < H) {
            for (int ce = 0; ce < cl; ce++) {
                float v = s_e[ce * H + tid];
                float mn = fmaxf(m_run, v);
                z_run = z_run * expf(m_run - mn) + expf(v - mn);
                m_run = mn;
            }
        }
        __syncthreads();
    }
    if (tid < H) { s_m[tid] = m_run; s_z[tid] = z_run; }
    __syncthreads();

    // Pass B: alpha-weighted vectorized gather of h[src]
    float acc[VW];
#pragma unroll
    for (int v = 0; v < VW; v++) acc[v] = 0.f;
    const int hh_t = (tid * VW) / C;

    for (int c0 = 0; c0 < deg; c0 += CH) {
        int cl = min(CH, deg - c0);
        if (tid < cl) s_src[tid] = g_csr[e0 + c0 + tid];
        __syncthreads();
        for (int idx = tid; idx < cl * H; idx += NT) {
            int ce = idx / H, hh = idx - ce * H;
            float v = g_hs[s_src[ce] * H + hh] + s_hdi[hh];
            v = v > 0.f ? v : 0.2f * v;
            s_e[idx] = expf(v - s_m[hh]) / (s_z[hh] + 1e-16f);
        }
        __syncthreads();
        if (tid < NV) {
            for (int ce = 0; ce < cl; ce++) {
                const __half* hrow = g_hbufh + (size_t)s_src[ce] * HC + tid * VW;
                float al = s_e[ce * H + hh_t];
                if (VW == 8) {
                    uint4 pk = *(const uint4*)hrow;
                    float2 f0 = __half22float2(*(__half2*)&pk.x);
                    float2 f1 = __half22float2(*(__half2*)&pk.y);
                    float2 f2 = __half22float2(*(__half2*)&pk.z);
                    float2 f3 = __half22float2(*(__half2*)&pk.w);
                    acc[0] += al * f0.x; acc[1] += al * f0.y;
                    acc[2] += al * f1.x; acc[3] += al * f1.y;
                    acc[4] += al * f2.x; acc[5] += al * f2.y;
                    acc[6] += al * f3.x; acc[7] += al * f3.y;
                } else if (VW == 4) {
                    uint2 pk = *(const uint2*)hrow;
                    float2 f0 = __half22float2(*(__half2*)&pk.x);
                    float2 f1 = __half22float2(*(__half2*)&pk.y);
                    acc[0] += al * f0.x; acc[1] += al * f0.y;
                    acc[2] += al * f1.x; acc[3] += al * f1.y;
                } else {
                    float2 f0 = __half22float2(*(const __half2*)hrow);
                    acc[0] += al * f0.x; acc[1] += al * f0.y;
                }
            }
        }
        __syncthreads();
    }

    if (tid < NV) {
#pragma unroll
        for (int v = 0; v < VW; v++) s_agg[tid * VW + v] = acc[v];
    }
    __syncthreads();

    unsigned char f = g_bflags[i];
    for (int c = tid; c < C; c += NT) {
        float v = 0.f;
#pragma unroll
        for (int hh = 0; hh < H; hh++) v += s_agg[hh * C + c];
        v = v * (1.f / H) + bias[c];
        v = selu_f(v);
        if (FINAL) v += x[i * 10 + c];
        if (c == 0)      v = (f & 2) ? 0.f : ((f & 1) ? 1.f : v);
        else if (c == 1) v = (f & 8) ? 1.f : ((f & 4) ? 0.f : v);
        if (FINAL) outp[(size_t)i * C + c] = v;
        else       g_feath[(size_t)i * C + c] = __float2half(v);
    }
}

// ---------------- host launch ----------------
extern "C" void kernel_launch(void* const* d_in, const int* in_sizes, int n_in,
                              void* d_out, int out_size) {
    const float* x  = (const float*)d_in[0];
    const void*  ei = d_in[1];
    const float* cf = (const float*)d_in[2];
    const float* cw[4]  = {(const float*)d_in[3], (const float*)d_in[5],
                           (const float*)d_in[7], (const float*)d_in[9]};
    const float* cbi[4] = {(const float*)d_in[4], (const float*)d_in[6],
                           (const float*)d_in[8], (const float*)d_in[10]};
    const float *gw[5], *gas[5], *gad[5], *gb[5];
    for (int l = 0; l < 5; l++) {
        gw[l]  = (const float*)d_in[11 + 4 * l];
        gas[l] = (const float*)d_in[12 + 4 * l];
        gad[l] = (const float*)d_in[13 + 4 * l];
        gb[l]  = (const float*)d_in[14 + 4 * l];
    }
    float* out = (float*)d_out;

    const int fins[5] = {34, 64, 128, 256, 128};
    const int Kps[5]  = {64, 64, 128, 256, 128};
    const int Hs[5]   = {8, 16, 8, 8, 16};
    const int Cs[5]   = {64, 128, 256, 128, 2};
    int woff[5];
    {
        int o = 0;
        for (int l = 0; l < 5; l++) { woff[l] = o; o += Hs[l] * Cs[l] * Kps[l]; }
    }

    init_detect_k<<<(NN + 255) / 256, 256>>>(ei);
    csr_count_k<<<(NE + 255) / 256, 256>>>(ei);

    // all weight conversions up front (off the layer critical path)
    for (int l = 0; l < 5; l++) {
        int cnt = Hs[l] * Cs[l] * Kps[l];
        wconv_k<<<(cnt + 255) / 256, 256>>>(gw[l], fins[l], Hs[l] * Cs[l], Kps[l], woff[l]);
    }

    csr_scan_k<<<1, 1024>>>();
    csr_fill_k<<<(ET + 255) / 256, 256>>>(ei);

    conv3x3_k<<<dim3(16, 16), 256>>>(cf, 0, 1, cw[0], cbi[0], 4);
    conv3x3_k<<<dim3(16, 32), 256>>>(nullptr, 1, 2, cw[1], cbi[1], 16);
    conv3x3_k<<<dim3(16, 64), 256>>>(nullptr, 2, 1, cw[2], cbi[2], 32);
    conv3x3_k<<<dim3(16, 24), 256>>>(nullptr, 1, 2, cw[3], cbi[3], 64);
    avgpool_k<<<24, 256>>>();
    build_in_k<<<(NN + 255) / 256, 256>>>(x);

    for (int l = 0; l < 5; l++) {
        int HC = Hs[l] * Cs[l];
        int Kp = Kps[l];
        dim3 gg((HC + 63) / 64, (NN + 127) / 128);
        hgemm_k<<<gg, 256>>>(Kp, HC, woff[l]);
        attn_dots_k<<<NN, 256>>>(gas[l], gad[l], Hs[l], Cs[l]);
        switch (l) {
            case 0: gat_agg_k<8, 64, 2, false><<<NN, 256>>>(gb[0], x, nullptr); break;
            case 1: gat_agg_k<16, 128, 8, false><<<NN, 256>>>(gb[1], x, nullptr); break;
            case 2: gat_agg_k<8, 256, 8, false><<<NN, 256>>>(gb[2], x, nullptr); break;
            case 3: gat_agg_k<8, 128, 4, false><<<NN, 256>>>(gb[3], x, nullptr); break;
            case 4: gat_agg_k<16, 2, 2, true><<<NN, 256>>>(gb[4], x, out); break;
        }
    }
}

// round 17
// speedup vs baseline: 1.6436x; 1.0245x over previous
#include <cuda_runtime.h>
#include <cuda_fp16.h>
#include <math.h>
#include <stdint.h>

#define NN 10000
#define NE 160000
#define ET (NN + NE)

// ---------------- scratch (device globals; referenced by symbol ONLY in device code) ----------------
__device__ __half g_feath[NN * 256];    // layer input features fp16 (row-major, stride = Kp)
__device__ __half g_wh[1048576];        // all layers' W^T fp16, [HC][Kp] K-major, packed
__device__ __half g_hbufh[NN * 2048];   // h = X @ W  fp16 (row-major, stride = H*C)
__device__ float  g_hs[NN * 16];
__device__ float  g_hd[NN * 16];
__device__ int    g_cnt[NN];
__device__ int    g_cur[NN];
__device__ int    g_off[NN + 1];
__device__ int    g_csr[ET];
__device__ float  g_cb1[64 * 64 * 64];
__device__ float  g_cb2[64 * 64 * 64];
__device__ float  g_gf[24];
__device__ unsigned char g_bflags[NN];
__device__ int    g_is64;

__device__ __forceinline__ float selu_f(float v) {
    const float sc = 1.0507009873554805f;
    const float al = 1.6732632423543772f;
    return v > 0.f ? sc * v : sc * al * (expf(v) - 1.f);
}

__device__ __forceinline__ int edge_at(const void* ei, int idx) {
    if (g_is64) return (int)((const long long*)ei)[idx];
    return ((const int*)ei)[idx];
}

__device__ __forceinline__ uint32_t smem_u32(const void* p) {
    uint32_t a;
    asm("{ .reg .u64 t; cvta.to.shared.u64 t, %1; cvt.u32.u64 %0, t; }" : "=r"(a) : "l"(p));
    return a;
}

// ---------------- CSR init + dtype detection ----------------
__global__ void init_detect_k(const void* __restrict__ ei) {
    int i = blockIdx.x * 256 + threadIdx.x;
    if (i < NN) { g_cnt[i] = 1; g_cur[i] = 0; }
    if (blockIdx.x == 0) {
        __shared__ int nz;
        if (threadIdx.x == 0) nz = 0;
        __syncthreads();
        const int* p = (const int*)ei;
        int found = 0;
        for (int j = threadIdx.x; j < 4096; j += 256)
            if (p[2 * j + 1] != 0) found = 1;
        if (found) atomicOr(&nz, 1);
        __syncthreads();
        if (threadIdx.x == 0) g_is64 = nz ? 0 : 1;
    }
}

__global__ void csr_count_k(const void* __restrict__ ei) {
    int e = blockIdx.x * 256 + threadIdx.x;
    if (e < NE) atomicAdd(&g_cnt[edge_at(ei, NE + e)], 1);
}

__global__ void csr_scan_k() {
    __shared__ int wsum[32];
    int tid = threadIdx.x;
    const int per = 10;
    int start = tid * per;
    int s = 0;
#pragma unroll
    for (int j = 0; j < per; j++) { int idx = start + j; if (idx < NN) s += g_cnt[idx]; }
    int lane = tid & 31, warp = tid >> 5;
    int v = s;
#pragma unroll
    for (int o = 1; o < 32; o <<= 1) {
        int t = __shfl_up_sync(0xffffffffu, v, o);
        if (lane >= o) v += t;
    }
    if (lane == 31) wsum[warp] = v;
    __syncthreads();
    if (warp == 0) {
        int w = wsum[lane];
#pragma unroll
        for (int o = 1; o < 32; o <<= 1) {
            int t = __shfl_up_sync(0xffffffffu, w, o);
            if (lane >= o) w += t;
        }
        wsum[lane] = w;
    }
    __syncthreads();
    int base = (warp ? wsum[warp - 1] : 0) + (v - s);
    int run = base;
#pragma unroll
    for (int j = 0; j < per; j++) {
        int idx = start + j;
        if (idx < NN) { g_off[idx] = run; run += g_cnt[idx]; }
    }
    if (tid == 0) g_off[NN] = wsum[31];
}

__global__ void csr_fill_k(const void* __restrict__ ei) {
    int idx = blockIdx.x * 256 + threadIdx.x;
    if (idx >= ET) return;
    int s, d;
    if (idx < NN) { s = idx; d = idx; }
    else {
        int e = idx - NN;
        s = edge_at(ei, e);
        d = edge_at(ei, NE + e);
    }
    int pos = g_off[d] + atomicAdd(&g_cur[d], 1);
    g_csr[pos] = s;
}

// ---------------- CNN ----------------
__global__ void conv3x3_k(const float* __restrict__ ext_in, int in_sel, int out_sel,
                          const float* __restrict__ w, const float* __restrict__ b, int IC) {
    __shared__ float ws[64 * 9];
    const float* in = (in_sel == 0) ? ext_in : (in_sel == 1 ? g_cb1 : g_cb2);
    float* out = (out_sel == 1) ? g_cb1 : g_cb2;
    int oc = blockIdx.y;
    for (int idx = threadIdx.x; idx < IC * 9; idx += 256) ws[idx] = w[oc * IC * 9 + idx];
    __syncthreads();
    int p = blockIdx.x * 256 + threadIdx.x;
    int y = p >> 6, xx = p & 63;
    float acc = b[oc];
    for (int ic = 0; ic < IC; ic++) {
        const float* ip = in + ic * 4096;
        const float* wp = ws + ic * 9;
#pragma unroll
        for (int ky = 0; ky < 3; ky++) {
            int iy = y + ky - 1;
            if ((unsigned)iy >= 64u) continue;
#pragma unroll
            for (int kx = 0; kx < 3; kx++) {
                int ix = xx + kx - 1;
                if ((unsigned)ix >= 64u) continue;
                acc += ip[iy * 64 + ix] * wp[ky * 3 + kx];
            }
        }
    }
    out[oc * 4096 + p] = selu_f(acc);
}

__global__ void avgpool_k() {
    __shared__ float red[256];
    int c = blockIdx.x;
    float s = 0.f;
    for (int p = threadIdx.x; p < 4096; p += 256) s += g_cb2[c * 4096 + p];
    red[threadIdx.x] = s;
    __syncthreads();
    for (int o = 128; o > 0; o >>= 1) {
        if (threadIdx.x < o) red[threadIdx.x] += red[threadIdx.x + o];
        __syncthreads();
    }
    if (threadIdx.x == 0) g_gf[c] = red[0] * (1.f / 4096.f);
}

// layer-1 input (fp16, Kp=64 padded) + boundary flags
__global__ void build_in_k(const float* __restrict__ x) {
    int i = blockIdx.x * 256 + threadIdx.x;
    if (i >= NN) return;
    float x0 = x[i * 10], x1 = x[i * 10 + 1];
    unsigned char f = 0;
    if (x0 == 1.f) f |= 1;
    if (x0 == 0.f) f |= 2;
    if (x1 == 0.f) f |= 4;
    if (x1 == 1.f) f |= 8;
    g_bflags[i] = f;
    __half* row = g_feath + i * 64;
#pragma unroll
    for (int c = 0; c < 24; c++) row[c] = __float2half(g_gf[c]);
#pragma unroll
    for (int c = 0; c < 10; c++) row[24 + c] = __float2half(x[i * 10 + c]);
#pragma unroll
    for (int c = 34; c < 64; c++) row[c] = __float2half(0.f);
}

// ---------------- weight conversion: W[K][HC] fp32 -> g_wh[woff + n*Kp + k] fp16 ----------------
__global__ void wconv_k(const float* __restrict__ W, int K, int HC, int Kp, int woff) {
    int idx = blockIdx.x * 256 + threadIdx.x;
    if (idx >= HC * Kp) return;
    int n = idx / Kp, kp = idx - n * Kp;
    float f = (kp < K) ? W[(size_t)kp * HC + n] : 0.f;
    g_wh[woff + idx] = __float2half(f);
}

// ---------------- fp16 tensor-core GEMM v4: 128x128 block, double-buffered + ldmatrix ----------------
__device__ __forceinline__ void mma_f16(float& c0, float& c1, float& c2, float& c3,
                                        uint32_t a0, uint32_t a1, uint32_t a2, uint32_t a3,
                                        uint32_t b0, uint32_t b1) {
    asm volatile(
        "mma.sync.aligned.m16n8k16.row.col.f32.f16.f16.f32 "
        "{%0,%1,%2,%3}, {%4,%5,%6,%7}, {%8,%9}, {%0,%1,%2,%3};"
        : "+f"(c0), "+f"(c1), "+f"(c2), "+f"(c3)
        : "r"(a0), "r"(a1), "r"(a2), "r"(a3), "r"(b0), "r"(b1));
}

__device__ __forceinline__ void ldsm4(uint32_t& r0, uint32_t& r1, uint32_t& r2, uint32_t& r3,
                                      uint32_t addr) {
    asm volatile("ldmatrix.sync.aligned.m8n8.x4.shared.b16 {%0,%1,%2,%3}, [%4];"
                 : "=r"(r0), "=r"(r1), "=r"(r2), "=r"(r3) : "r"(addr));
}

__global__ void __launch_bounds__(256) hgemm_k(int Kp, int M, int woff) {
    // Block 128(M) x 128(N); 8 warps 2(M) x 4(N); warp tile 64x32; BK=32, double-buffered.
    __shared__ alignas(16) __half As[2][128][40];
    __shared__ alignas(16) __half Bs[2][128][40];

    const int tid = threadIdx.x;
    const int wid = tid >> 5, lane = tid & 31;
    const int group = lane >> 2, tig = lane & 3;
    const int warpM = wid & 1, warpN = wid >> 1;
    const int row0 = blockIdx.y * 128, col0 = blockIdx.x * 128;

    float acc[4][4][4];
#pragma unroll
    for (int mf = 0; mf < 4; mf++)
#pragma unroll
        for (int nf = 0; nf < 4; nf++)
#pragma unroll
            for (int r = 0; r < 4; r++) acc[mf][nf][r] = 0.f;

    const int aq = tid & 3;
    const uint32_t asb = smem_u32(As);
    const uint32_t bsb = smem_u32(Bs);
    constexpr uint32_t ABUF = 128 * 40 * 2;
    constexpr uint32_t BBUF = 128 * 40 * 2;
    // A: lane l -> row = warpM*64 + (l&15) (+mf*16), col = (l>>4)*8 (+ks*16)
    const uint32_t aoff = ((uint32_t)(warpM * 64 + (lane & 15)) * 40 + ((lane >> 4) << 3)) * 2;
    // B: lane l -> row = warpN*32 + (l&7) + ((l>>4)&1)*8 (+pair*16), col = ((l>>3)&1)*8 (+ks*16)
    const uint32_t boff = ((uint32_t)(warpN * 32 + (lane & 7) + (((lane >> 4) & 1) << 3)) * 40 +
                           (((lane >> 3) & 1) << 3)) * 2;

    uint4 raA[2], raB[2];
    auto gload = [&](int kt) {
        int k0 = kt * 32;
#pragma unroll
        for (int p = 0; p < 2; p++) {
            int r = (tid >> 2) + p * 64;
            int gr = row0 + r;
            raA[p] = make_uint4(0, 0, 0, 0);
            if (gr < NN) raA[p] = *(const uint4*)&g_feath[(size_t)gr * Kp + k0 + aq * 8];
            int gc = col0 + r;
            raB[p] = make_uint4(0, 0, 0, 0);
            if (gc < M) raB[p] = *(const uint4*)&g_wh[woff + (size_t)gc * Kp + k0 + aq * 8];
        }
    };
    auto sstore = [&](int buf) {
#pragma unroll
        for (int p = 0; p < 2; p++) {
            int r = (tid >> 2) + p * 64;
            *(uint4*)&As[buf][r][aq * 8] = raA[p];
            *(uint4*)&Bs[buf][r][aq * 8] = raB[p];
        }
    };

    const int ntiles = Kp >> 5;
    gload(0);
    sstore(0);
    __syncthreads();

    for (int kt = 0; kt < ntiles; kt++) {
        int buf = kt & 1;
        bool more = (kt + 1 < ntiles);
        if (more) gload(kt + 1);
        uint32_t abase = asb + buf * ABUF + aoff;
        uint32_t bbase = bsb + buf * BBUF + boff;
#pragma unroll
        for (int ks = 0; ks < 2; ks++) {
            uint32_t koffB = (uint32_t)(ks * 16 * 2);
            uint32_t a[4][4], b0[4], b1[4];
#pragma unroll
            for (int mf = 0; mf < 4; mf++)
                ldsm4(a[mf][0], a[mf][1], a[mf][2], a[mf][3],
                      abase + (uint32_t)(mf * 16 * 40 * 2) + koffB);
            ldsm4(b0[0], b0[1], b0[2], b0[3], bbase + koffB);                 // nf 0,1
            ldsm4(b1[0], b1[1], b1[2], b1[3], bbase + 16 * 40 * 2 + koffB);   // nf 2,3
            uint32_t bf[4][2] = {{b0[0], b0[1]}, {b0[2], b0[3]}, {b1[0], b1[1]}, {b1[2], b1[3]}};
#pragma unroll
            for (int mf = 0; mf < 4; mf++)
#pragma unroll
                for (int nf = 0; nf < 4; nf++) {
                    float* c = acc[mf][nf];
                    mma_f16(c[0], c[1], c[2], c[3],
                            a[mf][0], a[mf][1], a[mf][2], a[mf][3], bf[nf][0], bf[nf][1]);
                }
        }
        if (more) sstore(buf ^ 1);
        __syncthreads();
    }

    // epilogue
#pragma unroll
    for (int mf = 0; mf < 4; mf++) {
        int rbase = row0 + warpM * 64 + mf * 16 + group;
#pragma unroll
        for (int nf = 0; nf < 4; nf++) {
            int cbase = col0 + warpN * 32 + nf * 8 + 2 * tig;
            if (cbase < M) {
                if (rbase < NN) {
                    __half2 h = __floats2half2_rn(acc[mf][nf][0], acc[mf][nf][1]);
                    *(__half2*)&g_hbufh[(size_t)rbase * M + cbase] = h;
                }
                if (rbase + 8 < NN) {
                    __half2 h = __floats2half2_rn(acc[mf][nf][2], acc[mf][nf][3]);
                    *(__half2*)&g_hbufh[(size_t)(rbase + 8) * M + cbase] = h;
                }
            }
        }
    }
}

// ---------------- per-node attention dots hs/hd (reads g_hbufh) ----------------
__global__ void attn_dots_k(const float* __restrict__ as_, const float* __restrict__ ad_,
                            int H, int C) {
    int i = blockIdx.x;
    int warp = threadIdx.x >> 5, lane = threadIdx.x & 31;
    const __half2* hrow = (const __half2*)(g_hbufh + (size_t)i * H * C);
    int C2 = C >> 1;
    for (int hh = warp; hh < H; hh += 8) {
        float ps = 0.f, pd = 0.f;
        for (int c2 = lane; c2 < C2; c2 += 32) {
            float2 f = __half22float2(hrow[hh * C2 + c2]);
            int c = 2 * c2;
            ps += f.x * as_[hh * C + c] + f.y * as_[hh * C + c + 1];
            pd += f.x * ad_[hh * C + c] + f.y * ad_[hh * C + c + 1];
        }
#pragma unroll
        for (int o = 16; o; o >>= 1) {
            ps += __shfl_xor_sync(0xffffffffu, ps, o);
            pd += __shfl_xor_sync(0xffffffffu, pd, o);
        }
        if (lane == 0) { g_hs[i * H + hh] = ps; g_hd[i * H + hh] = pd; }
    }
}

// ---------------- GAT aggregation v2: cached edge scores + warp softmax ----------------
template <int H, int C, int VW, bool FINAL>
__global__ void gat_agg_k(const float* __restrict__ bias, const float* __restrict__ x,
                          float* __restrict__ outp) {
    constexpr int HC = H * C;
    constexpr int NT = 256;
    constexpr int NV = HC / VW;
    constexpr int EMAX = 128;
    constexpr int CH = 32;
    static_assert(NV <= NT, "vector coverage");
    __shared__ float s_m[H], s_z[H], s_hdi[H];
    __shared__ int   s_src[EMAX];
    __shared__ float s_e[EMAX * H];
    __shared__ float s_agg[HC];

    int i = blockIdx.x;
    int tid = threadIdx.x;
    int lane = tid & 31, warp = tid >> 5;
    int e0 = g_off[i];
    int deg = g_off[i + 1] - e0;
    if (tid < H) s_hdi[tid] = g_hd[i * H + tid];
    __syncthreads();

    float acc[VW];
#pragma unroll
    for (int v = 0; v < VW; v++) acc[v] = 0.f;
    const int hh_t = (tid * VW) / C;

    if (deg <= EMAX) {
        // ---- fast path: all edges cached ----
        for (int ce = tid; ce < deg; ce += NT) s_src[ce] = g_csr[e0 + ce];
        __syncthreads();
        for (int idx = tid; idx < deg * H; idx += NT) {
            int ce = idx / H, hh = idx - ce * H;
            float v = g_hs[s_src[ce] * H + hh] + s_hdi[hh];
            s_e[idx] = v > 0.f ? v : 0.2f * v;
        }
        __syncthreads();
        // per-head warp softmax stats
        for (int hh = warp; hh < H; hh += 8) {
            float m = -1e30f;
            for (int ce = lane; ce < deg; ce += 32) m = fmaxf(m, s_e[ce * H + hh]);
#pragma unroll
            for (int o = 16; o; o >>= 1) m = fmaxf(m, __shfl_xor_sync(0xffffffffu, m, o));
            float z = 0.f;
            for (int ce = lane; ce < deg; ce += 32) z += expf(s_e[ce * H + hh] - m);
#pragma unroll
            for (int o = 16; o; o >>= 1) z += __shfl_xor_sync(0xffffffffu, z, o);
            if (lane == 0) { s_m[hh] = m; s_z[hh] = z; }
        }
        __syncthreads();
        // convert scores to alphas in place
        for (int idx = tid; idx < deg * H; idx += NT) {
            int hh = idx % H;
            s_e[idx] = expf(s_e[idx] - s_m[hh]) / (s_z[hh] + 1e-16f);
        }
        __syncthreads();
        // gather
        if (tid < NV) {
            for (int ce = 0; ce < deg; ce++) {
                const __half* hrow = g_hbufh + (size_t)s_src[ce] * HC + tid * VW;
                float al = s_e[ce * H + hh_t];
                if (VW == 8) {
                    uint4 pk = *(const uint4*)hrow;
                    float2 f0 = __half22float2(*(__half2*)&pk.x);
                    float2 f1 = __half22float2(*(__half2*)&pk.y);
                    float2 f2 = __half22float2(*(__half2*)&pk.z);
                    float2 f3 = __half22float2(*(__half2*)&pk.w);
                    acc[0] += al * f0.x; acc[1] += al * f0.y;
                    acc[2] += al * f1.x; acc[3] += al * f1.y;
                    acc[4] += al * f2.x; acc[5] += al * f2.y;
                    acc[6] += al * f3.x; acc[7] += al * f3.y;
                } else if (VW == 4) {
                    uint2 pk = *(const uint2*)hrow;
                    float2 f0 = __half22float2(*(__half2*)&pk.x);
                    float2 f1 = __half22float2(*(__half2*)&pk.y);
                    acc[0] += al * f0.x; acc[1] += al * f0.y;
                    acc[2] += al * f1.x; acc[3] += al * f1.y;
                } else {
                    float2 f0 = __half22float2(*(const __half2*)hrow);
                    acc[0] += al * f0.x; acc[1] += al * f0.y;
                }
            }
        }
        __syncthreads();
    } else {
        // ---- fallback: chunked two-pass (rare) ----
        float m_run = -1e30f, z_run = 0.f;
        for (int c0 = 0; c0 < deg; c0 += CH) {
            int cl = min(CH, deg - c0);
            if (tid < cl) s_src[tid] = g_csr[e0 + c0 + tid];
            __syncthreads();
            for (int idx = tid; idx < cl * H; idx += NT) {
                int ce = idx / H, hh = idx - ce * H;
                float v = g_hs[s_src[ce] * H + hh] + s_hdi[hh];
                s_e[idx] = v > 0.f ? v : 0.2f * v;
            }
            __syncthreads();
            if (tid < H) {
                for (int ce = 0; ce < cl; ce++) {
                    float v = s_e[ce * H + tid];
                    float mn = fmaxf(m_run, v);
                    z_run = z_run * expf(m_run - mn) + expf(v - mn);
                    m_run = mn;
                }
            }
            __syncthreads();
        }
        if (tid < H) { s_m[tid] = m_run; s_z[tid] = z_run; }
        __syncthreads();
        for (int c0 = 0; c0 < deg; c0 += CH) {
            int cl = min(CH, deg - c0);
            if (tid < cl) s_src[tid] = g_csr[e0 + c0 + tid];
            __syncthreads();
            for (int idx = tid; idx < cl * H; idx += NT) {
                int ce = idx / H, hh = idx - ce * H;
                float v = g_hs[s_src[ce] * H + hh] + s_hdi[hh];
                v = v > 0.f ? v : 0.2f * v;
                s_e[idx] = expf(v - s_m[hh]) / (s_z[hh] + 1e-16f);
            }
            __syncthreads();
            if (tid < NV) {
                for (int ce = 0; ce < cl; ce++) {
                    const __half* hrow = g_hbufh + (size_t)s_src[ce] * HC + tid * VW;
                    float al = s_e[ce * H + hh_t];
                    if (VW == 8) {
                        uint4 pk = *(const uint4*)hrow;
                        float2 f0 = __half22float2(*(__half2*)&pk.x);
                        float2 f1 = __half22float2(*(__half2*)&pk.y);
                        float2 f2 = __half22float2(*(__half2*)&pk.z);
                        float2 f3 = __half22float2(*(__half2*)&pk.w);
                        acc[0] += al * f0.x; acc[1] += al * f0.y;
                        acc[2] += al * f1.x; acc[3] += al * f1.y;
                        acc[4] += al * f2.x; acc[5] += al * f2.y;
                        acc[6] += al * f3.x; acc[7] += al * f3.y;
                    } else if (VW == 4) {
                        uint2 pk = *(const uint2*)hrow;
                        float2 f0 = __half22float2(*(__half2*)&pk.x);
                        float2 f1 = __half22float2(*(__half2*)&pk.y);
                        acc[0] += al * f0.x; acc[1] += al * f0.y;
                        acc[2] += al * f1.x; acc[3] += al * f1.y;
                    } else {
                        float2 f0 = __half22float2(*(const __half2*)hrow);
                        acc[0] += al * f0.x; acc[1] += al * f0.y;
                    }
                }
            }
            __syncthreads();
        }
    }

    if (tid < NV) {
#pragma unroll
        for (int v = 0; v < VW; v++) s_agg[tid * VW + v] = acc[v];
    }
    __syncthreads();

    unsigned char f = g_bflags[i];
    for (int c = tid; c < C; c += NT) {
        float v = 0.f;
#pragma unroll
        for (int hh = 0; hh < H; hh++) v += s_agg[hh * C + c];
        v = v * (1.f / H) + bias[c];
        v = selu_f(v);
        if (FINAL) v += x[i * 10 + c];
        if (c == 0)      v = (f & 2) ? 0.f : ((f & 1) ? 1.f : v);
        else if (c == 1) v = (f & 8) ? 1.f : ((f & 4) ? 0.f : v);
        if (FINAL) outp[(size_t)i * C + c] = v;
        else       g_feath[(size_t)i * C + c] = __float2half(v);
    }
}

// ---------------- host launch ----------------
extern "C" void kernel_launch(void* const* d_in, const int* in_sizes, int n_in,
                              void* d_out, int out_size) {
    const float* x  = (const float*)d_in[0];
    const void*  ei = d_in[1];
    const float* cf = (const float*)d_in[2];
    const float* cw[4]  = {(const float*)d_in[3], (const float*)d_in[5],
                           (const float*)d_in[7], (const float*)d_in[9]};
    const float* cbi[4] = {(const float*)d_in[4], (const float*)d_in[6],
                           (const float*)d_in[8], (const float*)d_in[10]};
    const float *gw[5], *gas[5], *gad[5], *gb[5];
    for (int l = 0; l < 5; l++) {
        gw[l]  = (const float*)d_in[11 + 4 * l];
        gas[l] = (const float*)d_in[12 + 4 * l];
        gad[l] = (const float*)d_in[13 + 4 * l];
        gb[l]  = (const float*)d_in[14 + 4 * l];
    }
    float* out = (float*)d_out;

    const int fins[5] = {34, 64, 128, 256, 128};
    const int Kps[5]  = {64, 64, 128, 256, 128};
    const int Hs[5]   = {8, 16, 8, 8, 16};
    const int Cs[5]   = {64, 128, 256, 128, 2};
    int woff[5];
    {
        int o = 0;
        for (int l = 0; l < 5; l++) { woff[l] = o; o += Hs[l] * Cs[l] * Kps[l]; }
    }

    init_detect_k<<<(NN + 255) / 256, 256>>>(ei);
    csr_count_k<<<(NE + 255) / 256, 256>>>(ei);

    for (int l = 0; l < 5; l++) {
        int cnt = Hs[l] * Cs[l] * Kps[l];
        wconv_k<<<(cnt + 255) / 256, 256>>>(gw[l], fins[l], Hs[l] * Cs[l], Kps[l], woff[l]);
    }

    csr_scan_k<<<1, 1024>>>();
    csr_fill_k<<<(ET + 255) / 256, 256>>>(ei);

    conv3x3_k<<<dim3(16, 16), 256>>>(cf, 0, 1, cw[0], cbi[0], 4);
    conv3x3_k<<<dim3(16, 32), 256>>>(nullptr, 1, 2, cw[1], cbi[1], 16);
    conv3x3_k<<<dim3(16, 64), 256>>>(nullptr, 2, 1, cw[2], cbi[2], 32);
    conv3x3_k<<<dim3(16, 24), 256>>>(nullptr, 1, 2, cw[3], cbi[3], 64);
    avgpool_k<<<24, 256>>>();
    build_in_k<<<(NN + 255) / 256, 256>>>(x);

    for (int l = 0; l < 5; l++) {
        int HC = Hs[l] * Cs[l];
        int Kp = Kps[l];
        dim3 gg((HC + 127) / 128, (NN + 127) / 128);
        hgemm_k<<<gg, 256>>>(Kp, HC, woff[l]);
        attn_dots_k<<<NN, 256>>>(gas[l], gad[l], Hs[l], Cs[l]);
        switch (l) {
            case 0: gat_agg_k<8, 64, 2, false><<<NN, 256>>>(gb[0], x, nullptr); break;
            case 1: gat_agg_k<16, 128, 8, false><<<NN, 256>>>(gb[1], x, nullptr); break;
            case 2: gat_agg_k<8, 256, 8, false><<<NN, 256>>>(gb[2], x, nullptr); break;
            case 3: gat_agg_k<8, 128, 4, false><<<NN, 256>>>(gb[3], x, nullptr); break;
            case 4: gat_agg_k<16, 2, 2, true><<<NN, 256>>>(gb[4], x, out); break;
        }
    }
}